// round 6
// baseline (speedup 1.0000x reference)
#include <cuda_runtime.h>
#include <cuda_bf16.h>

// OrdinalRegressionLoss: mean over B x 4 of
//   max(x,0) - x*[j < target] + log1p(exp(-|x|))
// B = 8,388,608 rows, logits fp32 (B,4), targets int32 (B,).
// 160 MiB streamed once -> HBM-bound.
// Measured-best direction: dense contiguous chunk per thread.
// This round: 8 rows/thread (128B logits + 32B targets), one-wave grid,
// fused threadfence-reduction tail.

#define NBLOCKS 592           // 148 SMs * 4 blocks, one wave
#define NTHREADS 256
#define ROWS_PER_THREAD 8

__device__ float g_partials[NBLOCKS];
__device__ unsigned int g_count = 0;   // reset by last block -> graph-replay safe

__device__ __forceinline__ float bce_term(float x, float y) {
    float ax = fabsf(x);
    float sp = __logf(1.0f + __expf(-ax));   // log1p(exp(-ax)), ax>=0
    return fmaxf(x, 0.0f) - x * y + sp;
}

__device__ __forceinline__ float row_loss(float4 l, int t) {
    float s = bce_term(l.x, (float)(0 < t));
    s += bce_term(l.y, (float)(1 < t));
    s += bce_term(l.z, (float)(2 < t));
    s += bce_term(l.w, (float)(3 < t));
    return s;
}

__device__ __forceinline__ float block_reduce(float acc, float* ws) {
    #pragma unroll
    for (int o = 16; o > 0; o >>= 1)
        acc += __shfl_down_sync(0xffffffffu, acc, o);
    int lane = threadIdx.x & 31;
    int wid  = threadIdx.x >> 5;
    if (lane == 0) ws[wid] = acc;
    __syncthreads();
    float v = 0.0f;
    if (wid == 0) {
        v = (lane < NTHREADS / 32) ? ws[lane] : 0.0f;
        #pragma unroll
        for (int o = 4; o > 0; o >>= 1)
            v += __shfl_down_sync(0xffffffffu, v, o);
    }
    return v;   // valid at (wid==0, lane==0)
}

__global__ void __launch_bounds__(NTHREADS, 4)
ordinal_loss_fused(const float4* __restrict__ logits4,
                   const int* __restrict__ targets,
                   int nrows, float inv_total, float* __restrict__ out) {
    __shared__ float ws[NTHREADS / 32];
    __shared__ bool is_last;

    float acc = 0.0f;
    int ngroups = nrows / ROWS_PER_THREAD;
    int stride = gridDim.x * blockDim.x;
    const int4* targets4 = (const int4*)targets;

    for (int g = blockIdx.x * blockDim.x + threadIdx.x; g < ngroups; g += stride) {
        // 10 independent streaming loads: thread owns a dense 128B+32B chunk.
        const float4* lp = logits4 + (size_t)g * ROWS_PER_THREAD;
        float4 l0 = __ldcs(lp + 0);
        float4 l1 = __ldcs(lp + 1);
        float4 l2 = __ldcs(lp + 2);
        float4 l3 = __ldcs(lp + 3);
        float4 l4 = __ldcs(lp + 4);
        float4 l5 = __ldcs(lp + 5);
        float4 l6 = __ldcs(lp + 6);
        float4 l7 = __ldcs(lp + 7);
        int4 ta = __ldcs(targets4 + g * 2 + 0);
        int4 tb = __ldcs(targets4 + g * 2 + 1);
        acc += row_loss(l0, ta.x);
        acc += row_loss(l1, ta.y);
        acc += row_loss(l2, ta.z);
        acc += row_loss(l3, ta.w);
        acc += row_loss(l4, tb.x);
        acc += row_loss(l5, tb.y);
        acc += row_loss(l6, tb.z);
        acc += row_loss(l7, tb.w);
    }
    // tail rows (nrows % 8) — B=8388608 is divisible by 8; guard for safety.
    int rem_base = ngroups * ROWS_PER_THREAD;
    for (int r = rem_base + blockIdx.x * blockDim.x + threadIdx.x; r < nrows; r += stride)
        acc += row_loss(__ldcs(logits4 + r), __ldcs(targets + r));

    float bsum = block_reduce(acc, ws);
    if (threadIdx.x == 0) {
        g_partials[blockIdx.x] = bsum;
        __threadfence();
        unsigned int old = atomicAdd(&g_count, 1u);
        is_last = (old == gridDim.x - 1);
    }
    __syncthreads();

    if (is_last) {
        float a = 0.0f;
        for (int j = threadIdx.x; j < (int)gridDim.x; j += NTHREADS)
            a += g_partials[j];
        __syncthreads();          // ws reuse hazard
        float total = block_reduce(a, ws);
        if (threadIdx.x == 0) {
            out[0] = total * inv_total;
            g_count = 0;          // reset for next graph replay
        }
    }
}

extern "C" void kernel_launch(void* const* d_in, const int* in_sizes, int n_in,
                              void* d_out, int out_size) {
    const float4* logits4 = (const float4*)d_in[0];   // (B,4) fp32
    const int* targets    = (const int*)d_in[1];      // (B,) int32 on device
    float* out = (float*)d_out;

    int nrows = in_sizes[1];                          // B
    float inv_total = 1.0f / ((float)nrows * 4.0f);

    ordinal_loss_fused<<<NBLOCKS, NTHREADS>>>(logits4, targets, nrows, inv_total, out);
}

// round 7
// speedup vs baseline: 1.2636x; 1.2636x over previous
#include <cuda_runtime.h>
#include <cuda_bf16.h>

// OrdinalRegressionLoss: mean over B x 4 of
//   max(x,0) - x*[j < target] + log1p(exp(-|x|))
// B = 8,388,608 rows, logits fp32 (B,4), targets int32 (B,).
// 160 MiB streamed once -> HBM-bound.
// Measured sweet spot: 4 consecutive rows/thread (R3 = 31.2us @ 48% occ).
// This round: same body, 5 blocks/SM (occ 60%), one-wave grid = 740 blocks.

#define NBLOCKS 740           // 148 SMs * 5 blocks, one wave
#define NTHREADS 256

__device__ float g_partials[NBLOCKS];
__device__ unsigned int g_count = 0;   // reset by last block -> graph-replay safe

__device__ __forceinline__ float bce_term(float x, float y) {
    float ax = fabsf(x);
    float sp = __logf(1.0f + __expf(-ax));   // log1p(exp(-ax)), ax>=0
    return fmaxf(x, 0.0f) - x * y + sp;
}

__device__ __forceinline__ float row_loss(float4 l, int t) {
    float s = bce_term(l.x, (float)(0 < t));
    s += bce_term(l.y, (float)(1 < t));
    s += bce_term(l.z, (float)(2 < t));
    s += bce_term(l.w, (float)(3 < t));
    return s;
}

__device__ __forceinline__ float block_reduce(float acc, float* ws) {
    #pragma unroll
    for (int o = 16; o > 0; o >>= 1)
        acc += __shfl_down_sync(0xffffffffu, acc, o);
    int lane = threadIdx.x & 31;
    int wid  = threadIdx.x >> 5;
    if (lane == 0) ws[wid] = acc;
    __syncthreads();
    float v = 0.0f;
    if (wid == 0) {
        v = (lane < NTHREADS / 32) ? ws[lane] : 0.0f;
        #pragma unroll
        for (int o = 4; o > 0; o >>= 1)
            v += __shfl_down_sync(0xffffffffu, v, o);
    }
    return v;   // valid at (wid==0, lane==0)
}

__global__ void __launch_bounds__(NTHREADS, 5)
ordinal_loss_fused(const float4* __restrict__ logits4,
                   const int* __restrict__ targets,
                   int nrows, float inv_total, float* __restrict__ out) {
    __shared__ float ws[NTHREADS / 32];
    __shared__ bool is_last;

    float acc = 0.0f;
    int ngroups = nrows >> 2;                 // 4 rows per group
    int stride = gridDim.x * blockDim.x;
    const int4* targets4 = (const int4*)targets;

    for (int g = blockIdx.x * blockDim.x + threadIdx.x; g < ngroups; g += stride) {
        // Thread owns a dense 64B+16B chunk: 5 independent streaming loads.
        float4 l0 = __ldcs(logits4 + g * 4 + 0);
        float4 l1 = __ldcs(logits4 + g * 4 + 1);
        float4 l2 = __ldcs(logits4 + g * 4 + 2);
        float4 l3 = __ldcs(logits4 + g * 4 + 3);
        int4   t4 = __ldcs(targets4 + g);
        acc += row_loss(l0, t4.x);
        acc += row_loss(l1, t4.y);
        acc += row_loss(l2, t4.z);
        acc += row_loss(l3, t4.w);
    }
    // tail rows (nrows % 4) — guard for safety
    int rem_base = ngroups << 2;
    int r = rem_base + blockIdx.x * blockDim.x + threadIdx.x;
    if (r < nrows)
        acc += row_loss(__ldcs(logits4 + r), __ldcs(targets + r));

    float bsum = block_reduce(acc, ws);
    if (threadIdx.x == 0) {
        g_partials[blockIdx.x] = bsum;
        __threadfence();
        unsigned int old = atomicAdd(&g_count, 1u);
        is_last = (old == gridDim.x - 1);
    }
    __syncthreads();

    if (is_last) {
        float a = 0.0f;
        for (int j = threadIdx.x; j < (int)gridDim.x; j += NTHREADS)
            a += g_partials[j];
        __syncthreads();          // ws reuse hazard
        float total = block_reduce(a, ws);
        if (threadIdx.x == 0) {
            out[0] = total * inv_total;
            g_count = 0;          // reset for next graph replay
        }
    }
}

extern "C" void kernel_launch(void* const* d_in, const int* in_sizes, int n_in,
                              void* d_out, int out_size) {
    const float4* logits4 = (const float4*)d_in[0];   // (B,4) fp32
    const int* targets    = (const int*)d_in[1];      // (B,) int32 on device
    float* out = (float*)d_out;

    int nrows = in_sizes[1];                          // B
    float inv_total = 1.0f / ((float)nrows * 4.0f);

    ordinal_loss_fused<<<NBLOCKS, NTHREADS>>>(logits4, targets, nrows, inv_total, out);
}